// round 9
// baseline (speedup 1.0000x reference)
#include <cuda_runtime.h>
#include <math.h>

// out[row] = tanh(sqrt(sum_j (w[row][j] - x[j])^2)), row in [0, 1048576), j in [0, 256)
// Champion structure (2 rows/warp, 4 front-batched coalesced 512B streaming
// loads) with x served from SHARED memory: the per-warp x LDGs were L1-hit
// broadcasts but still consumed L1tex wavefront-queue slots ahead of the
// DRAM-bound weight loads (single per-SM FIFO). Serving x via LDS removes
// 33% of global-path queue entries per warp.

__global__ __launch_bounds__(256) void sonia_l2_tanh_smemx(
    const float* __restrict__ x,
    const float* __restrict__ w,
    float* __restrict__ out,
    int n_rows)
{
    __shared__ float xs[256];

    // Cooperative 1KB load of x: one float per thread, coalesced.
    xs[threadIdx.x] = x[threadIdx.x];
    __syncthreads();

    const int warp_id = (blockIdx.x * blockDim.x + threadIdx.x) >> 5;
    const int lane    = threadIdx.x & 31;
    const int row0    = warp_id * 2;
    if (row0 >= n_rows) return;

    const float4* __restrict__ wr = reinterpret_cast<const float4*>(w) + (size_t)row0 * 64;

    // 4 independent streaming loads (evict-first: pure pass-through data).
    // Issued BEFORE the LDS reads so they hit the L1tex queue immediately.
    const float4 a0 = __ldcs(wr + lane);
    const float4 a1 = __ldcs(wr + lane + 32);
    const float4 b0 = __ldcs(wr + lane + 64);
    const float4 b1 = __ldcs(wr + lane + 96);

    // x from shared memory: LDS.128, conflict-free (lane l -> bytes [16l,16l+16)).
    const float4* xsv = reinterpret_cast<const float4*>(xs);
    const float4 x0 = xsv[lane];
    const float4 x1 = xsv[lane + 32];

    float d;
    float sa = 0.0f, sb = 0.0f;
    d = a0.x - x0.x; sa = fmaf(d, d, sa);
    d = a0.y - x0.y; sa = fmaf(d, d, sa);
    d = a0.z - x0.z; sa = fmaf(d, d, sa);
    d = a0.w - x0.w; sa = fmaf(d, d, sa);
    d = a1.x - x1.x; sa = fmaf(d, d, sa);
    d = a1.y - x1.y; sa = fmaf(d, d, sa);
    d = a1.z - x1.z; sa = fmaf(d, d, sa);
    d = a1.w - x1.w; sa = fmaf(d, d, sa);

    d = b0.x - x0.x; sb = fmaf(d, d, sb);
    d = b0.y - x0.y; sb = fmaf(d, d, sb);
    d = b0.z - x0.z; sb = fmaf(d, d, sb);
    d = b0.w - x0.w; sb = fmaf(d, d, sb);
    d = b1.x - x1.x; sb = fmaf(d, d, sb);
    d = b1.y - x1.y; sb = fmaf(d, d, sb);
    d = b1.z - x1.z; sb = fmaf(d, d, sb);
    d = b1.w - x1.w; sb = fmaf(d, d, sb);

    // Butterfly reduce both sums across the warp.
    #pragma unroll
    for (int off = 16; off > 0; off >>= 1) {
        sa += __shfl_xor_sync(0xFFFFFFFFu, sa, off);
        sb += __shfl_xor_sync(0xFFFFFFFFu, sb, off);
    }

    if (lane == 0) {
        out[row0]     = tanhf(sqrtf(sa));
        if (row0 + 1 < n_rows)
            out[row0 + 1] = tanhf(sqrtf(sb));
    }
}

extern "C" void kernel_launch(void* const* d_in, const int* in_sizes, int n_in,
                              void* d_out, int out_size)
{
    const float* x = (const float*)d_in[0];   // input  [1, 256]
    const float* w = (const float*)d_in[1];   // weight [out_size, 256]
    float* out     = (float*)d_out;

    const int n_rows = out_size;              // 1048576
    // 8 warps/block, 2 rows/warp -> 16 rows per block
    const int rows_per_block = 16;
    const int blocks = (n_rows + rows_per_block - 1) / rows_per_block;

    sonia_l2_tanh_smemx<<<blocks, 256>>>(x, w, out, n_rows);
}

// round 10
// speedup vs baseline: 1.0002x; 1.0002x over previous
#include <cuda_runtime.h>
#include <math.h>

// out[row] = tanh(sqrt(sum_j (w[row][j] - x[j])^2)), row in [0, 1048576), j in [0, 256)
//
// FINAL (champion since R2: 149.98us best, 150-152 noise band, DRAM 90.7-91.8%,
// 7.2-7.27 TB/s = this chip's effective streaming ceiling for a 1.07 GB
// read-once pattern). Warp handles TWO rows via 4 independent front-batched
// 128-bit evict-first streaming loads, each a fully-coalesced 512B warp
// transaction; x stays L1-resident via __ldg. 32 regs, occ ~78%.
// Probes that did NOT beat it: deeper per-warp MLP (reg-staged at 32reg,
// occupancy-traded at 48reg), persistent+prefetch, block=512, packed stores,
// smem-served x. The kernel is memory-roofline-bound; bytes are irreducible.

__global__ __launch_bounds__(256) void sonia_l2_tanh_kernel2(
    const float* __restrict__ x,
    const float* __restrict__ w,
    float* __restrict__ out,
    int n_rows)
{
    const int warp_id = (blockIdx.x * blockDim.x + threadIdx.x) >> 5;
    const int lane    = threadIdx.x & 31;
    const int row0    = warp_id * 2;
    if (row0 >= n_rows) return;

    const float4* __restrict__ wr = reinterpret_cast<const float4*>(w) + (size_t)row0 * 64;
    const float4* __restrict__ xr = reinterpret_cast<const float4*>(x);

    // x is tiny and re-read by every warp: L1/L2 resident.
    const float4 x0 = __ldg(xr + lane);
    const float4 x1 = __ldg(xr + lane + 32);

    // 4 independent streaming loads (evict-first: pure pass-through data).
    const float4 a0 = __ldcs(wr + lane);
    const float4 a1 = __ldcs(wr + lane + 32);
    const float4 b0 = __ldcs(wr + lane + 64);
    const float4 b1 = __ldcs(wr + lane + 96);

    float d;
    float sa = 0.0f, sb = 0.0f;
    d = a0.x - x0.x; sa = fmaf(d, d, sa);
    d = a0.y - x0.y; sa = fmaf(d, d, sa);
    d = a0.z - x0.z; sa = fmaf(d, d, sa);
    d = a0.w - x0.w; sa = fmaf(d, d, sa);
    d = a1.x - x1.x; sa = fmaf(d, d, sa);
    d = a1.y - x1.y; sa = fmaf(d, d, sa);
    d = a1.z - x1.z; sa = fmaf(d, d, sa);
    d = a1.w - x1.w; sa = fmaf(d, d, sa);

    d = b0.x - x0.x; sb = fmaf(d, d, sb);
    d = b0.y - x0.y; sb = fmaf(d, d, sb);
    d = b0.z - x0.z; sb = fmaf(d, d, sb);
    d = b0.w - x0.w; sb = fmaf(d, d, sb);
    d = b1.x - x1.x; sb = fmaf(d, d, sb);
    d = b1.y - x1.y; sb = fmaf(d, d, sb);
    d = b1.z - x1.z; sb = fmaf(d, d, sb);
    d = b1.w - x1.w; sb = fmaf(d, d, sb);

    // Butterfly reduce both sums across the warp.
    #pragma unroll
    for (int off = 16; off > 0; off >>= 1) {
        sa += __shfl_xor_sync(0xFFFFFFFFu, sa, off);
        sb += __shfl_xor_sync(0xFFFFFFFFu, sb, off);
    }

    if (lane == 0) {
        out[row0]     = tanhf(sqrtf(sa));
        if (row0 + 1 < n_rows)
            out[row0 + 1] = tanhf(sqrtf(sb));
    }
}

extern "C" void kernel_launch(void* const* d_in, const int* in_sizes, int n_in,
                              void* d_out, int out_size)
{
    const float* x = (const float*)d_in[0];   // input  [1, 256]
    const float* w = (const float*)d_in[1];   // weight [out_size, 256]
    float* out     = (float*)d_out;

    const int n_rows = out_size;              // 1048576
    // 8 warps/block, 2 rows/warp -> 16 rows per block
    const int rows_per_block = 16;
    const int blocks = (n_rows + rows_per_block - 1) / rows_per_block;

    sonia_l2_tanh_kernel2<<<blocks, 256>>>(x, w, out, n_rows);
}

// round 11
// speedup vs baseline: 1.0015x; 1.0013x over previous
#include <cuda_runtime.h>
#include <math.h>

// out[row] = tanh(sqrt(sum_j (w[row][j] - x[j])^2)), row in [0, 1048576), j in [0, 256)
//
// FINAL — memory-roofline-bound champion (best sample 149.98us; 150-152 noise
// band measured across three identical-binary runs; DRAM 89.8-91.8%, i.e.
// 7.1-7.27 TB/s, this chip's effective ceiling for a 1.07 GB read-once stream).
//
// Structure: warp handles TWO rows via 4 independent front-batched 128-bit
// evict-first streaming loads (each a fully-coalesced 512B warp transaction);
// x stays L1-resident via __ldg; warp-shuffle butterfly reduction; scalar
// tanh(sqrt()) epilogue on lane 0. 32 regs, occ ~78%.
//
// Exhausted probes (all neutral/negative, each diagnosed): 8-load MLP at
// 32-reg budget (ptxas staged loads), 8-load MLP at 48 regs (occupancy
// traded 1:1), persistent grid + software prefetch (grid/SM mismatch +
// pipeline exposure), block=512, packed float2 stores (epilogue reschedule
// cost 6% DRAM), smem-served x (L1tex queue hypothesis falsified).
// Bytes are irreducible; the kernel is at the wall.

__global__ __launch_bounds__(256) void sonia_l2_tanh_kernel2(
    const float* __restrict__ x,
    const float* __restrict__ w,
    float* __restrict__ out,
    int n_rows)
{
    const int warp_id = (blockIdx.x * blockDim.x + threadIdx.x) >> 5;
    const int lane    = threadIdx.x & 31;
    const int row0    = warp_id * 2;
    if (row0 >= n_rows) return;

    const float4* __restrict__ wr = reinterpret_cast<const float4*>(w) + (size_t)row0 * 64;
    const float4* __restrict__ xr = reinterpret_cast<const float4*>(x);

    // x is tiny and re-read by every warp: L1/L2 resident.
    const float4 x0 = __ldg(xr + lane);
    const float4 x1 = __ldg(xr + lane + 32);

    // 4 independent streaming loads (evict-first: pure pass-through data).
    const float4 a0 = __ldcs(wr + lane);
    const float4 a1 = __ldcs(wr + lane + 32);
    const float4 b0 = __ldcs(wr + lane + 64);
    const float4 b1 = __ldcs(wr + lane + 96);

    float d;
    float sa = 0.0f, sb = 0.0f;
    d = a0.x - x0.x; sa = fmaf(d, d, sa);
    d = a0.y - x0.y; sa = fmaf(d, d, sa);
    d = a0.z - x0.z; sa = fmaf(d, d, sa);
    d = a0.w - x0.w; sa = fmaf(d, d, sa);
    d = a1.x - x1.x; sa = fmaf(d, d, sa);
    d = a1.y - x1.y; sa = fmaf(d, d, sa);
    d = a1.z - x1.z; sa = fmaf(d, d, sa);
    d = a1.w - x1.w; sa = fmaf(d, d, sa);

    d = b0.x - x0.x; sb = fmaf(d, d, sb);
    d = b0.y - x0.y; sb = fmaf(d, d, sb);
    d = b0.z - x0.z; sb = fmaf(d, d, sb);
    d = b0.w - x0.w; sb = fmaf(d, d, sb);
    d = b1.x - x1.x; sb = fmaf(d, d, sb);
    d = b1.y - x1.y; sb = fmaf(d, d, sb);
    d = b1.z - x1.z; sb = fmaf(d, d, sb);
    d = b1.w - x1.w; sb = fmaf(d, d, sb);

    // Butterfly reduce both sums across the warp.
    #pragma unroll
    for (int off = 16; off > 0; off >>= 1) {
        sa += __shfl_xor_sync(0xFFFFFFFFu, sa, off);
        sb += __shfl_xor_sync(0xFFFFFFFFu, sb, off);
    }

    if (lane == 0) {
        out[row0]     = tanhf(sqrtf(sa));
        if (row0 + 1 < n_rows)
            out[row0 + 1] = tanhf(sqrtf(sb));
    }
}

extern "C" void kernel_launch(void* const* d_in, const int* in_sizes, int n_in,
                              void* d_out, int out_size)
{
    const float* x = (const float*)d_in[0];   // input  [1, 256]
    const float* w = (const float*)d_in[1];   // weight [out_size, 256]
    float* out     = (float*)d_out;

    const int n_rows = out_size;              // 1048576
    // 8 warps/block, 2 rows/warp -> 16 rows per block
    const int rows_per_block = 16;
    const int blocks = (n_rows + rows_per_block - 1) / rows_per_block;

    sonia_l2_tanh_kernel2<<<blocks, 256>>>(x, w, out, n_rows);
}